// round 16
// baseline (speedup 1.0000x reference)
#include <cuda_runtime.h>
#include <cuda_bf16.h>
#include <cstdint>

// BiGRU: B=64, S=4096, D_in=7, H=128, 2 layers, bidirectional, fp32.
//   k_gx0    : gx0 = x @ Wih0^T + bih0 (both dirs)     -> g_gx [tok][768]
//   k_rec    : R14 recurrence + shortened gate dependency chain:
//              r/z pre-activations pre-scaled by 0.5 in producers; sigmoid
//              affine form distributed so constants compute parallel to MUFU
//   k_gemm_tc: gx1 = h1in @ Wih1^T + bih1 (R15: bf16 split + fragment reuse)
//   k_rec    : layer 1
//   k_head   : logits = h1out @ wout^T + bout

#define BB   64
#define SS   4096
#define DIN  7
#define HH   128
#define G3   384
#define NTOK (BB * SS)          // 262144

// ---------------- scratch (device globals; reused across phases) -------------
__device__ float g_gx [ (size_t)NTOK * 768 ];   // gate pre-activations [f384|b384]
__device__ float g_hio[ (size_t)NTOK * 256 ];   // layer in/out hidden  [f128|b128]

// ---------------- f32x2 helpers ----------------------------------------------
__device__ __forceinline__ unsigned long long ffma2(unsigned long long a,
                                                    unsigned long long b,
                                                    unsigned long long c) {
    unsigned long long d;
    asm("fma.rn.f32x2 %0, %1, %2, %3;" : "=l"(d) : "l"(a), "l"(b), "l"(c));
    return d;
}
__device__ __forceinline__ float2 unpk(unsigned long long v) {
    float2 r;
    asm("mov.b64 {%0, %1}, %2;" : "=f"(r.x), "=f"(r.y) : "l"(v));
    return r;
}
__device__ __forceinline__ float htanh(float x) {      // HW MUFU tanh (sm_75+)
    float y;
    asm("tanh.approx.f32 %0, %1;" : "=f"(y) : "f"(x));
    return y;
}

// ---------------- warp-MMA helpers (baseline PTX, sm_80+) ---------------------
__device__ __forceinline__ uint32_t smem_u32(const void* p) {
    uint32_t a;
    asm("{ .reg .u64 t; cvta.to.shared.u64 t, %1; cvt.u32.u64 %0, t; }"
        : "=r"(a) : "l"(p));
    return a;
}
__device__ __forceinline__ void ldmx4(uint32_t& r0, uint32_t& r1,
                                      uint32_t& r2, uint32_t& r3, uint32_t addr) {
    asm volatile("ldmatrix.sync.aligned.m8n8.x4.shared.b16 {%0,%1,%2,%3}, [%4];"
                 : "=r"(r0), "=r"(r1), "=r"(r2), "=r"(r3) : "r"(addr));
}
__device__ __forceinline__ void mma_bf16(float* d, const uint32_t* a,
                                         const uint32_t* b) {
    asm volatile("mma.sync.aligned.m16n8k16.row.col.f32.bf16.bf16.f32 "
                 "{%0,%1,%2,%3}, {%4,%5,%6,%7}, {%8,%9}, {%0,%1,%2,%3};"
                 : "+f"(d[0]), "+f"(d[1]), "+f"(d[2]), "+f"(d[3])
                 : "r"(a[0]), "r"(a[1]), "r"(a[2]), "r"(a[3]),
                   "r"(b[0]), "r"(b[1]));
}

// ---------------- layer-0 input projection (K=7) ------------------------------
__global__ void k_gx0(const float* __restrict__ x,
                      const float* __restrict__ wf, const float* __restrict__ bf,
                      const float* __restrict__ wb, const float* __restrict__ bb) {
    __shared__ float sx[8 * DIN];
    int j = threadIdx.x;                       // 0..767
    long long token0 = (long long)blockIdx.x * 8;
    int dir = (j >= G3);
    int jj = dir ? j - G3 : j;
    const float* wrow = (dir ? wb : wf) + jj * DIN;
    float w0 = wrow[0], w1 = wrow[1], w2 = wrow[2], w3 = wrow[3];
    float w4 = wrow[4], w5 = wrow[5], w6 = wrow[6];
    float bias = (dir ? bb : bf)[jj];
    if (j < 8 * DIN) sx[j] = x[token0 * DIN + j];
    __syncthreads();
#pragma unroll
    for (int tk = 0; tk < 8; tk++) {
        const float* xs = sx + tk * DIN;
        float v = bias;
        v = fmaf(w0, xs[0], v); v = fmaf(w1, xs[1], v); v = fmaf(w2, xs[2], v);
        v = fmaf(w3, xs[3], v); v = fmaf(w4, xs[4], v); v = fmaf(w5, xs[5], v);
        v = fmaf(w6, xs[6], v);
        g_gx[(token0 + tk) * 768 + j] = v;
    }
}

// ---------------- recurrence (MUFU gates, shortened serial chain) -------------
// r/z rows publish 0.5*(gh+gx): sigmoid(x) = 0.5*tanh(x/2)+0.5 needs only the
// pre-scaled arg. Gate math distributed so every op not depending on a MUFU
// result runs in parallel with it:
//   n  = tanh( tr*(0.5*hn) + (0.5*hn + xn) )
//   h' = tz*(0.5*h - 0.5*n) + (0.5*h + 0.5*n)
__global__ void __launch_bounds__(384, 1) k_rec(
    const float* __restrict__ whh_f, const float* __restrict__ bhh_f,
    const float* __restrict__ whh_b, const float* __restrict__ bhh_b) {
    __shared__ __align__(16) float s_h[HH];
    __shared__ float s_b[G3];
    __shared__ float s_xn[HH];

    int j   = threadIdx.x;
    int b   = blockIdx.x >> 1;
    int dir = blockIdx.x & 1;

    const float* whh = dir ? whh_b : whh_f;
    float bhh = (dir ? bhh_b : bhh_f)[j];

    unsigned long long w[64];
    const unsigned long long* wp =
        (const unsigned long long*)(whh + (size_t)j * HH);
#pragma unroll
    for (int i = 0; i < 64; i++) w[i] = wp[i];

    if (j < HH) s_h[j] = 0.f;
    float hreg = 0.f;

    long long tokbase = (long long)b * SS;
    int t0 = dir ? (SS - 1) : 0;
    long long gstr = dir ? -768 : 768;
    long long hstr = dir ? -256 : 256;

    const float* gp = g_gx + (tokbase + t0) * 768 + (long long)dir * G3 + j;
    float*       hp = g_hio + (tokbase + t0) * 256 + (long long)dir * HH + j;

    float gx_n1 = gp[0];
    gp += gstr;
    float gx_n2 = gp[0];
    __syncthreads();

    for (int tt = 0; tt < SS; tt++) {
        float gxv = gx_n1;
        gx_n1 = gx_n2;
        gp += gstr;
        if (tt + 2 < SS) gx_n2 = *gp;           // 2-step-ahead prefetch

        unsigned long long a0 = 0ull, a1 = 0ull;
        const ulonglong2* hv = (const ulonglong2*)s_h;
#pragma unroll
        for (int k = 0; k < 32; k++) {
            ulonglong2 hk = hv[k];               // LDS.128, warp-uniform broadcast
            a0 = ffma2(w[2 * k],     hk.x, a0);
            a1 = ffma2(w[2 * k + 1], hk.y, a1);
        }
        float2 f0 = unpk(a0), f1 = unpk(a1);
        float gh = (f0.x + f0.y) + (f1.x + f1.y) + bhh;

        if (j < 2 * HH) {
            s_b[j] = 0.5f * (gh + gxv);          // r,z rows: pre-added AND pre-scaled
        } else {
            s_b[j] = gh;                         // n rows: keep hn separate
            s_xn[j - 2 * HH] = gxv;
        }
        __syncthreads();

        if (j < HH) {
            float tr = htanh(s_b[j]);            // MUFU; constants below overlap
            float tz = htanh(s_b[HH + j]);
            float hn2 = 0.5f * s_b[2 * HH + j];
            float cn  = hn2 + s_xn[j];           // parallel with MUFU(tr)
            float n   = htanh(fmaf(tr, hn2, cn));
            float hh  = 0.5f * hreg;             // parallel with MUFU chain
            float hm  = fmaf(-0.5f, n, hh);      // 0.5h - 0.5n
            float hp2 = fmaf( 0.5f, n, hh);      // 0.5h + 0.5n
            hreg = fmaf(tz, hm, hp2);            // = (1-z)n + z h
            s_h[j] = hreg;
            *hp = hreg;
            hp += hstr;
        }
        __syncthreads();
    }
}

// ---------------- layer-1 GEMM via mma.sync (bf16 3-term split) ----------------
// C[262144x768] = A[262144x256]*W^T + bias. CTA tile M=128, N=256 (grid.y=3),
// 8 warps as 2x4 (warp tile 64x64), K in 16 chunks of 16.
// Fragment reuse: Ah/Al/Bh/Bl loaded ONCE per chunk (16 ldmatrix.x4 vs 24).
#define ASTR 24          // smem row stride in bf16 elems (48B: aligned, no conflicts)

__global__ void __launch_bounds__(256, 1) k_gemm_tc(
    const float* __restrict__ Wf, const float* __restrict__ bf,
    const float* __restrict__ Wb, const float* __restrict__ bb) {
    __shared__ __align__(16) __nv_bfloat16 Ah[128][ASTR];
    __shared__ __align__(16) __nv_bfloat16 Al[128][ASTR];
    __shared__ __align__(16) __nv_bfloat16 Bh[256][ASTR];
    __shared__ __align__(16) __nv_bfloat16 Bl[256][ASTR];

    int tid = threadIdx.x, wid = tid >> 5, lane = tid & 31;
    long long m0 = (long long)blockIdx.x * 128;
    int n0 = blockIdx.y * 256;
    int wm = wid >> 2, wn = wid & 3;             // warp 64x64 tile at (wm*64, wn*64)

    uint32_t aoff = (uint32_t)(((wm * 64 + (lane & 15)) * ASTR + (lane >> 4) * 8) * 2);
    uint32_t boff = (uint32_t)(((wn * 64 + (lane & 7) + ((lane >> 4) << 3)) * ASTR
                                + ((lane >> 3) & 1) * 8) * 2);
    uint32_t ah_a = smem_u32(Ah) + aoff, al_a = smem_u32(Al) + aoff;
    uint32_t bh_a = smem_u32(Bh) + boff, bl_a = smem_u32(Bl) + boff;

    float acc[4][8][4];
#pragma unroll
    for (int i = 0; i < 4; i++)
#pragma unroll
        for (int jx = 0; jx < 8; jx++)
#pragma unroll
            for (int q = 0; q < 4; q++) acc[i][jx][q] = 0.f;

    float4 pA[2], pB[4];
#pragma unroll
    for (int i = 0; i < 2; i++) {
        int task = tid + i * 256, row = task >> 2, c4 = task & 3;
        pA[i] = *(const float4*)(g_hio + (m0 + row) * 256 + c4 * 4);
    }
#pragma unroll
    for (int i = 0; i < 4; i++) {
        int task = tid + i * 256, row = task >> 2, c4 = task & 3;
        int n = n0 + row;
        const float* src = (n < 384) ? (Wf + (size_t)n * 256)
                                     : (Wb + (size_t)(n - 384) * 256);
        pB[i] = *(const float4*)(src + c4 * 4);
    }

    for (int ck = 0; ck < 16; ck++) {
#pragma unroll
        for (int i = 0; i < 2; i++) {
            int task = tid + i * 256, row = task >> 2, c4 = task & 3;
            float4 v = pA[i];
            __nv_bfloat16 hx = __float2bfloat16(v.x), hy = __float2bfloat16(v.y);
            __nv_bfloat16 hz = __float2bfloat16(v.z), hw = __float2bfloat16(v.w);
            __nv_bfloat162 h01 = __halves2bfloat162(hx, hy);
            __nv_bfloat162 h23 = __halves2bfloat162(hz, hw);
            __nv_bfloat162 l01 = __halves2bfloat162(
                __float2bfloat16(v.x - __bfloat162float(hx)),
                __float2bfloat16(v.y - __bfloat162float(hy)));
            __nv_bfloat162 l23 = __halves2bfloat162(
                __float2bfloat16(v.z - __bfloat162float(hz)),
                __float2bfloat16(v.w - __bfloat162float(hw)));
            *(uint2*)&Ah[row][c4 * 4] = make_uint2(*(uint32_t*)&h01, *(uint32_t*)&h23);
            *(uint2*)&Al[row][c4 * 4] = make_uint2(*(uint32_t*)&l01, *(uint32_t*)&l23);
        }
#pragma unroll
        for (int i = 0; i < 4; i++) {
            int task = tid + i * 256, row = task >> 2, c4 = task & 3;
            float4 v = pB[i];
            __nv_bfloat16 hx = __float2bfloat16(v.x), hy = __float2bfloat16(v.y);
            __nv_bfloat16 hz = __float2bfloat16(v.z), hw = __float2bfloat16(v.w);
            __nv_bfloat162 h01 = __halves2bfloat162(hx, hy);
            __nv_bfloat162 h23 = __halves2bfloat162(hz, hw);
            __nv_bfloat162 l01 = __halves2bfloat162(
                __float2bfloat16(v.x - __bfloat162float(hx)),
                __float2bfloat16(v.y - __bfloat162float(hy)));
            __nv_bfloat162 l23 = __halves2bfloat162(
                __float2bfloat16(v.z - __bfloat162float(hz)),
                __float2bfloat16(v.w - __bfloat162float(hw)));
            *(uint2*)&Bh[row][c4 * 4] = make_uint2(*(uint32_t*)&h01, *(uint32_t*)&h23);
            *(uint2*)&Bl[row][c4 * 4] = make_uint2(*(uint32_t*)&l01, *(uint32_t*)&l23);
        }
        __syncthreads();

        if (ck + 1 < 16) {
            int kc = (ck + 1) * 16;
#pragma unroll
            for (int i = 0; i < 2; i++) {
                int task = tid + i * 256, row = task >> 2, c4 = task & 3;
                pA[i] = *(const float4*)(g_hio + (m0 + row) * 256 + kc + c4 * 4);
            }
#pragma unroll
            for (int i = 0; i < 4; i++) {
                int task = tid + i * 256, row = task >> 2, c4 = task & 3;
                int n = n0 + row;
                const float* src = (n < 384) ? (Wf + (size_t)n * 256)
                                             : (Wb + (size_t)(n - 384) * 256);
                pB[i] = *(const float4*)(src + kc + c4 * 4);
            }
        }

        // ---- load all fragments ONCE, then 3 terms from registers ----
        {
            uint32_t fah[4][4], fal[4][4];
#pragma unroll
            for (int mf = 0; mf < 4; mf++) {
                ldmx4(fah[mf][0], fah[mf][1], fah[mf][2], fah[mf][3],
                      ah_a + mf * (16 * ASTR * 2));
                ldmx4(fal[mf][0], fal[mf][1], fal[mf][2], fal[mf][3],
                      al_a + mf * (16 * ASTR * 2));
            }
            uint32_t fbh[8][2], fbl[8][2];
#pragma unroll
            for (int p = 0; p < 4; p++) {
                uint32_t r0, r1, r2, r3;
                ldmx4(r0, r1, r2, r3, bh_a + p * (16 * ASTR * 2));
                fbh[2 * p][0] = r0; fbh[2 * p][1] = r1;
                fbh[2 * p + 1][0] = r2; fbh[2 * p + 1][1] = r3;
                ldmx4(r0, r1, r2, r3, bl_a + p * (16 * ASTR * 2));
                fbl[2 * p][0] = r0; fbl[2 * p][1] = r1;
                fbl[2 * p + 1][0] = r2; fbl[2 * p + 1][1] = r3;
            }
#pragma unroll
            for (int mf = 0; mf < 4; mf++)
#pragma unroll
                for (int nf = 0; nf < 8; nf++)
                    mma_bf16(acc[mf][nf], fah[mf], fbh[nf]);   // Ah*Bh
#pragma unroll
            for (int mf = 0; mf < 4; mf++)
#pragma unroll
                for (int nf = 0; nf < 8; nf++)
                    mma_bf16(acc[mf][nf], fah[mf], fbl[nf]);   // Ah*Bl
#pragma unroll
            for (int mf = 0; mf < 4; mf++)
#pragma unroll
                for (int nf = 0; nf < 8; nf++)
                    mma_bf16(acc[mf][nf], fal[mf], fbh[nf]);   // Al*Bh
        }
        __syncthreads();
    }

    int g = lane >> 2, c2 = (lane & 3) * 2;
    float bias2[8][2];
#pragma unroll
    for (int nf = 0; nf < 8; nf++) {
        int col = n0 + wn * 64 + nf * 8 + c2;
        bias2[nf][0] = (col < 384) ? bf[col] : bb[col - 384];
        bias2[nf][1] = (col + 1 < 384) ? bf[col + 1] : bb[col + 1 - 384];
    }
#pragma unroll
    for (int mf = 0; mf < 4; mf++) {
        long long r0 = m0 + wm * 64 + mf * 16 + g;
#pragma unroll
        for (int nf = 0; nf < 8; nf++) {
            int col = n0 + wn * 64 + nf * 8 + c2;
            *(float2*)&g_gx[r0 * 768 + col] =
                make_float2(acc[mf][nf][0] + bias2[nf][0],
                            acc[mf][nf][1] + bias2[nf][1]);
            *(float2*)&g_gx[(r0 + 8) * 768 + col] =
                make_float2(acc[mf][nf][2] + bias2[nf][0],
                            acc[mf][nf][3] + bias2[nf][1]);
        }
    }
}

// ---------------- output head: logits = h1out @ wout^T + bout -----------------
__global__ void k_head(const float* __restrict__ wout,
                       const float* __restrict__ bout,
                       float* __restrict__ out) {
    int warp = threadIdx.x >> 5, lane = threadIdx.x & 31;
    long long token = (long long)blockIdx.x * 8 + warp;
    const float* hrow = g_hio + token * 256;
    float acc = 0.f;
#pragma unroll
    for (int i = 0; i < 8; i++) {
        int c = lane + i * 32;
        acc = fmaf(hrow[c], wout[c], acc);
    }
#pragma unroll
    for (int off = 16; off; off >>= 1)
        acc += __shfl_xor_sync(0xffffffffu, acc, off);
    if (lane == 0) out[token] = acc + bout[0];
}

// ---------------- launch ------------------------------------------------------
extern "C" void kernel_launch(void* const* d_in, const int* in_sizes, int n_in,
                              void* d_out, int out_size) {
    const float* x     = (const float*)d_in[0];
    const float* wih0f = (const float*)d_in[1];
    const float* whh0f = (const float*)d_in[2];
    const float* bih0f = (const float*)d_in[3];
    const float* bhh0f = (const float*)d_in[4];
    const float* wih0b = (const float*)d_in[5];
    const float* whh0b = (const float*)d_in[6];
    const float* bih0b = (const float*)d_in[7];
    const float* bhh0b = (const float*)d_in[8];
    const float* wih1f = (const float*)d_in[9];
    const float* whh1f = (const float*)d_in[10];
    const float* bih1f = (const float*)d_in[11];
    const float* bhh1f = (const float*)d_in[12];
    const float* wih1b = (const float*)d_in[13];
    const float* whh1b = (const float*)d_in[14];
    const float* bih1b = (const float*)d_in[15];
    const float* bhh1b = (const float*)d_in[16];
    const float* wout  = (const float*)d_in[17];
    const float* bout  = (const float*)d_in[18];
    float* out = (float*)d_out;

    k_gx0    <<<NTOK / 8, 768>>>(x, wih0f, bih0f, wih0b, bih0b);
    k_rec    <<<128, 384>>>(whh0f, bhh0f, whh0b, bhh0b);
    k_gemm_tc<<<dim3(2048, 3), 256>>>(wih1f, bih1f, wih1b, bih1b);
    k_rec    <<<128, 384>>>(whh1f, bhh1f, whh1b, bhh1b);
    k_head   <<<NTOK / 8, 256>>>(wout, bout, out);
}

// round 17
// speedup vs baseline: 1.0632x; 1.0632x over previous
#include <cuda_runtime.h>
#include <cuda_bf16.h>
#include <cstdint>

// BiGRU: B=64, S=4096, D_in=7, H=128, 2 layers, bidirectional, fp32.
//   k_gx0    : gx0 = x @ Wih0^T + bih0 (both dirs)     -> g_gx [tok][768]
//   k_rec    : R14-validated recurrence (MUFU gates)
//   k_gemm_tc: gx1 = h1in @ Wih1^T + bih1; bf16 3-term split with per-chunk
//              fragment reuse (Ah/Al/Bh/Bl loaded once, 16 ldmatrix vs 24)
//   k_rec    : layer 1
//   k_head   : logits = h1out @ wout^T + bout

#define BB   64
#define SS   4096
#define DIN  7
#define HH   128
#define G3   384
#define NTOK (BB * SS)          // 262144

// ---------------- scratch (device globals; reused across phases) -------------
__device__ float g_gx [ (size_t)NTOK * 768 ];   // gate pre-activations [f384|b384]
__device__ float g_hio[ (size_t)NTOK * 256 ];   // layer in/out hidden  [f128|b128]

// ---------------- f32x2 helpers ----------------------------------------------
__device__ __forceinline__ unsigned long long ffma2(unsigned long long a,
                                                    unsigned long long b,
                                                    unsigned long long c) {
    unsigned long long d;
    asm("fma.rn.f32x2 %0, %1, %2, %3;" : "=l"(d) : "l"(a), "l"(b), "l"(c));
    return d;
}
__device__ __forceinline__ float2 unpk(unsigned long long v) {
    float2 r;
    asm("mov.b64 {%0, %1}, %2;" : "=f"(r.x), "=f"(r.y) : "l"(v));
    return r;
}
__device__ __forceinline__ float htanh(float x) {      // HW MUFU tanh (sm_75+)
    float y;
    asm("tanh.approx.f32 %0, %1;" : "=f"(y) : "f"(x));
    return y;
}
__device__ __forceinline__ float hsig(float x) {       // sigmoid via MUFU tanh
    return fmaf(0.5f, htanh(0.5f * x), 0.5f);
}

// ---------------- warp-MMA helpers (baseline PTX, sm_80+) ---------------------
__device__ __forceinline__ uint32_t smem_u32(const void* p) {
    uint32_t a;
    asm("{ .reg .u64 t; cvta.to.shared.u64 t, %1; cvt.u32.u64 %0, t; }"
        : "=r"(a) : "l"(p));
    return a;
}
__device__ __forceinline__ void ldmx4(uint32_t& r0, uint32_t& r1,
                                      uint32_t& r2, uint32_t& r3, uint32_t addr) {
    asm volatile("ldmatrix.sync.aligned.m8n8.x4.shared.b16 {%0,%1,%2,%3}, [%4];"
                 : "=r"(r0), "=r"(r1), "=r"(r2), "=r"(r3) : "r"(addr));
}
__device__ __forceinline__ void mma_bf16(float* d, const uint32_t* a,
                                         const uint32_t* b) {
    asm volatile("mma.sync.aligned.m16n8k16.row.col.f32.bf16.bf16.f32 "
                 "{%0,%1,%2,%3}, {%4,%5,%6,%7}, {%8,%9}, {%0,%1,%2,%3};"
                 : "+f"(d[0]), "+f"(d[1]), "+f"(d[2]), "+f"(d[3])
                 : "r"(a[0]), "r"(a[1]), "r"(a[2]), "r"(a[3]),
                   "r"(b[0]), "r"(b[1]));
}

// ---------------- layer-0 input projection (K=7) ------------------------------
__global__ void k_gx0(const float* __restrict__ x,
                      const float* __restrict__ wf, const float* __restrict__ bf,
                      const float* __restrict__ wb, const float* __restrict__ bb) {
    __shared__ float sx[8 * DIN];
    int j = threadIdx.x;                       // 0..767
    long long token0 = (long long)blockIdx.x * 8;
    int dir = (j >= G3);
    int jj = dir ? j - G3 : j;
    const float* wrow = (dir ? wb : wf) + jj * DIN;
    float w0 = wrow[0], w1 = wrow[1], w2 = wrow[2], w3 = wrow[3];
    float w4 = wrow[4], w5 = wrow[5], w6 = wrow[6];
    float bias = (dir ? bb : bf)[jj];
    if (j < 8 * DIN) sx[j] = x[token0 * DIN + j];
    __syncthreads();
#pragma unroll
    for (int tk = 0; tk < 8; tk++) {
        const float* xs = sx + tk * DIN;
        float v = bias;
        v = fmaf(w0, xs[0], v); v = fmaf(w1, xs[1], v); v = fmaf(w2, xs[2], v);
        v = fmaf(w3, xs[3], v); v = fmaf(w4, xs[4], v); v = fmaf(w5, xs[5], v);
        v = fmaf(w6, xs[6], v);
        g_gx[(token0 + tk) * 768 + j] = v;
    }
}

// ---------------- recurrence (R14-validated; MUFU gates) ----------------------
__global__ void __launch_bounds__(384, 1) k_rec(
    const float* __restrict__ whh_f, const float* __restrict__ bhh_f,
    const float* __restrict__ whh_b, const float* __restrict__ bhh_b) {
    __shared__ __align__(16) float s_h[HH];
    __shared__ float s_b[G3];
    __shared__ float s_xn[HH];

    int j   = threadIdx.x;
    int b   = blockIdx.x >> 1;
    int dir = blockIdx.x & 1;

    const float* whh = dir ? whh_b : whh_f;
    float bhh = (dir ? bhh_b : bhh_f)[j];

    unsigned long long w[64];
    const unsigned long long* wp =
        (const unsigned long long*)(whh + (size_t)j * HH);
#pragma unroll
    for (int i = 0; i < 64; i++) w[i] = wp[i];

    if (j < HH) s_h[j] = 0.f;
    float hreg = 0.f;

    long long tokbase = (long long)b * SS;
    int t0 = dir ? (SS - 1) : 0;
    long long gstr = dir ? -768 : 768;
    long long hstr = dir ? -256 : 256;

    const float* gp = g_gx + (tokbase + t0) * 768 + (long long)dir * G3 + j;
    float*       hp = g_hio + (tokbase + t0) * 256 + (long long)dir * HH + j;

    float gx_n1 = gp[0];
    gp += gstr;
    float gx_n2 = gp[0];
    __syncthreads();

    for (int tt = 0; tt < SS; tt++) {
        float gxv = gx_n1;
        gx_n1 = gx_n2;
        gp += gstr;
        if (tt + 2 < SS) gx_n2 = *gp;           // 2-step-ahead prefetch

        unsigned long long a0 = 0ull, a1 = 0ull;
        const ulonglong2* hv = (const ulonglong2*)s_h;
#pragma unroll
        for (int k = 0; k < 32; k++) {
            ulonglong2 hk = hv[k];               // LDS.128, warp-uniform broadcast
            a0 = ffma2(w[2 * k],     hk.x, a0);
            a1 = ffma2(w[2 * k + 1], hk.y, a1);
        }
        float2 f0 = unpk(a0), f1 = unpk(a1);
        float gh = (f0.x + f0.y) + (f1.x + f1.y) + bhh;

        if (j < 2 * HH) {
            s_b[j] = gh + gxv;                   // r,z rows: pre-added
        } else {
            s_b[j] = gh;                         // n rows: keep hn separate
            s_xn[j - 2 * HH] = gxv;
        }
        __syncthreads();

        if (j < HH) {
            float r = hsig(s_b[j]);
            float z = hsig(s_b[HH + j]);
            float n = htanh(fmaf(r, s_b[2 * HH + j], s_xn[j]));
            hreg = fmaf(z, hreg - n, n);         // (1-z)*n + z*h
            s_h[j] = hreg;
            *hp = hreg;
            hp += hstr;
        }
        __syncthreads();
    }
}

// ---------------- layer-1 GEMM via mma.sync (bf16 3-term split) ----------------
// C[262144x768] = A[262144x256]*W^T + bias. CTA tile M=128, N=256 (grid.y=3),
// 8 warps as 2x4 (warp tile 64x64), K in 16 chunks of 16.
// Fragment reuse: Ah/Al/Bh/Bl loaded ONCE per chunk (16 ldmatrix.x4 vs 24),
// then 3 terms AhBh + AhBl + AlBh from registers.
#define ASTR 24          // smem row stride in bf16 elems (48B: aligned, no conflicts)

__global__ void __launch_bounds__(256, 1) k_gemm_tc(
    const float* __restrict__ Wf, const float* __restrict__ bf,
    const float* __restrict__ Wb, const float* __restrict__ bb) {
    __shared__ __align__(16) __nv_bfloat16 Ah[128][ASTR];
    __shared__ __align__(16) __nv_bfloat16 Al[128][ASTR];
    __shared__ __align__(16) __nv_bfloat16 Bh[256][ASTR];
    __shared__ __align__(16) __nv_bfloat16 Bl[256][ASTR];

    int tid = threadIdx.x, wid = tid >> 5, lane = tid & 31;
    long long m0 = (long long)blockIdx.x * 128;
    int n0 = blockIdx.y * 256;
    int wm = wid >> 2, wn = wid & 3;             // warp 64x64 tile at (wm*64, wn*64)

    uint32_t aoff = (uint32_t)(((wm * 64 + (lane & 15)) * ASTR + (lane >> 4) * 8) * 2);
    uint32_t boff = (uint32_t)(((wn * 64 + (lane & 7) + ((lane >> 4) << 3)) * ASTR
                                + ((lane >> 3) & 1) * 8) * 2);
    uint32_t ah_a = smem_u32(Ah) + aoff, al_a = smem_u32(Al) + aoff;
    uint32_t bh_a = smem_u32(Bh) + boff, bl_a = smem_u32(Bl) + boff;

    float acc[4][8][4];
#pragma unroll
    for (int i = 0; i < 4; i++)
#pragma unroll
        for (int jx = 0; jx < 8; jx++)
#pragma unroll
            for (int q = 0; q < 4; q++) acc[i][jx][q] = 0.f;

    float4 pA[2], pB[4];
#pragma unroll
    for (int i = 0; i < 2; i++) {
        int task = tid + i * 256, row = task >> 2, c4 = task & 3;
        pA[i] = *(const float4*)(g_hio + (m0 + row) * 256 + c4 * 4);
    }
#pragma unroll
    for (int i = 0; i < 4; i++) {
        int task = tid + i * 256, row = task >> 2, c4 = task & 3;
        int n = n0 + row;
        const float* src = (n < 384) ? (Wf + (size_t)n * 256)
                                     : (Wb + (size_t)(n - 384) * 256);
        pB[i] = *(const float4*)(src + c4 * 4);
    }

    for (int ck = 0; ck < 16; ck++) {
#pragma unroll
        for (int i = 0; i < 2; i++) {
            int task = tid + i * 256, row = task >> 2, c4 = task & 3;
            float4 v = pA[i];
            __nv_bfloat16 hx = __float2bfloat16(v.x), hy = __float2bfloat16(v.y);
            __nv_bfloat16 hz = __float2bfloat16(v.z), hw = __float2bfloat16(v.w);
            __nv_bfloat162 h01 = __halves2bfloat162(hx, hy);
            __nv_bfloat162 h23 = __halves2bfloat162(hz, hw);
            __nv_bfloat162 l01 = __halves2bfloat162(
                __float2bfloat16(v.x - __bfloat162float(hx)),
                __float2bfloat16(v.y - __bfloat162float(hy)));
            __nv_bfloat162 l23 = __halves2bfloat162(
                __float2bfloat16(v.z - __bfloat162float(hz)),
                __float2bfloat16(v.w - __bfloat162float(hw)));
            *(uint2*)&Ah[row][c4 * 4] = make_uint2(*(uint32_t*)&h01, *(uint32_t*)&h23);
            *(uint2*)&Al[row][c4 * 4] = make_uint2(*(uint32_t*)&l01, *(uint32_t*)&l23);
        }
#pragma unroll
        for (int i = 0; i < 4; i++) {
            int task = tid + i * 256, row = task >> 2, c4 = task & 3;
            float4 v = pB[i];
            __nv_bfloat16 hx = __float2bfloat16(v.x), hy = __float2bfloat16(v.y);
            __nv_bfloat16 hz = __float2bfloat16(v.z), hw = __float2bfloat16(v.w);
            __nv_bfloat162 h01 = __halves2bfloat162(hx, hy);
            __nv_bfloat162 h23 = __halves2bfloat162(hz, hw);
            __nv_bfloat162 l01 = __halves2bfloat162(
                __float2bfloat16(v.x - __bfloat162float(hx)),
                __float2bfloat16(v.y - __bfloat162float(hy)));
            __nv_bfloat162 l23 = __halves2bfloat162(
                __float2bfloat16(v.z - __bfloat162float(hz)),
                __float2bfloat16(v.w - __bfloat162float(hw)));
            *(uint2*)&Bh[row][c4 * 4] = make_uint2(*(uint32_t*)&h01, *(uint32_t*)&h23);
            *(uint2*)&Bl[row][c4 * 4] = make_uint2(*(uint32_t*)&l01, *(uint32_t*)&l23);
        }
        __syncthreads();

        if (ck + 1 < 16) {
            int kc = (ck + 1) * 16;
#pragma unroll
            for (int i = 0; i < 2; i++) {
                int task = tid + i * 256, row = task >> 2, c4 = task & 3;
                pA[i] = *(const float4*)(g_hio + (m0 + row) * 256 + kc + c4 * 4);
            }
#pragma unroll
            for (int i = 0; i < 4; i++) {
                int task = tid + i * 256, row = task >> 2, c4 = task & 3;
                int n = n0 + row;
                const float* src = (n < 384) ? (Wf + (size_t)n * 256)
                                             : (Wb + (size_t)(n - 384) * 256);
                pB[i] = *(const float4*)(src + kc + c4 * 4);
            }
        }

        // ---- load all fragments ONCE, then 3 terms from registers ----
        {
            uint32_t fah[4][4], fal[4][4];
#pragma unroll
            for (int mf = 0; mf < 4; mf++) {
                ldmx4(fah[mf][0], fah[mf][1], fah[mf][2], fah[mf][3],
                      ah_a + mf * (16 * ASTR * 2));
                ldmx4(fal[mf][0], fal[mf][1], fal[mf][2], fal[mf][3],
                      al_a + mf * (16 * ASTR * 2));
            }
            uint32_t fbh[8][2], fbl[8][2];
#pragma unroll
            for (int p = 0; p < 4; p++) {
                uint32_t r0, r1, r2, r3;
                ldmx4(r0, r1, r2, r3, bh_a + p * (16 * ASTR * 2));
                fbh[2 * p][0] = r0; fbh[2 * p][1] = r1;
                fbh[2 * p + 1][0] = r2; fbh[2 * p + 1][1] = r3;
                ldmx4(r0, r1, r2, r3, bl_a + p * (16 * ASTR * 2));
                fbl[2 * p][0] = r0; fbl[2 * p][1] = r1;
                fbl[2 * p + 1][0] = r2; fbl[2 * p + 1][1] = r3;
            }
#pragma unroll
            for (int mf = 0; mf < 4; mf++)
#pragma unroll
                for (int nf = 0; nf < 8; nf++)
                    mma_bf16(acc[mf][nf], fah[mf], fbh[nf]);   // Ah*Bh
#pragma unroll
            for (int mf = 0; mf < 4; mf++)
#pragma unroll
                for (int nf = 0; nf < 8; nf++)
                    mma_bf16(acc[mf][nf], fah[mf], fbl[nf]);   // Ah*Bl
#pragma unroll
            for (int mf = 0; mf < 4; mf++)
#pragma unroll
                for (int nf = 0; nf < 8; nf++)
                    mma_bf16(acc[mf][nf], fal[mf], fbh[nf]);   // Al*Bh
        }
        __syncthreads();
    }

    int g = lane >> 2, c2 = (lane & 3) * 2;
    float bias2[8][2];
#pragma unroll
    for (int nf = 0; nf < 8; nf++) {
        int col = n0 + wn * 64 + nf * 8 + c2;
        bias2[nf][0] = (col < 384) ? bf[col] : bb[col - 384];
        bias2[nf][1] = (col + 1 < 384) ? bf[col + 1] : bb[col + 1 - 384];
    }
#pragma unroll
    for (int mf = 0; mf < 4; mf++) {
        long long r0 = m0 + wm * 64 + mf * 16 + g;
#pragma unroll
        for (int nf = 0; nf < 8; nf++) {
            int col = n0 + wn * 64 + nf * 8 + c2;
            *(float2*)&g_gx[r0 * 768 + col] =
                make_float2(acc[mf][nf][0] + bias2[nf][0],
                            acc[mf][nf][1] + bias2[nf][1]);
            *(float2*)&g_gx[(r0 + 8) * 768 + col] =
                make_float2(acc[mf][nf][2] + bias2[nf][0],
                            acc[mf][nf][3] + bias2[nf][1]);
        }
    }
}

// ---------------- output head: logits = h1out @ wout^T + bout -----------------
__global__ void k_head(const float* __restrict__ wout,
                       const float* __restrict__ bout,
                       float* __restrict__ out) {
    int warp = threadIdx.x >> 5, lane = threadIdx.x & 31;
    long long token = (long long)blockIdx.x * 8 + warp;
    const float* hrow = g_hio + token * 256;
    float acc = 0.f;
#pragma unroll
    for (int i = 0; i < 8; i++) {
        int c = lane + i * 32;
        acc = fmaf(hrow[c], wout[c], acc);
    }
#pragma unroll
    for (int off = 16; off; off >>= 1)
        acc += __shfl_xor_sync(0xffffffffu, acc, off);
    if (lane == 0) out[token] = acc + bout[0];
}

// ---------------- launch ------------------------------------------------------
extern "C" void kernel_launch(void* const* d_in, const int* in_sizes, int n_in,
                              void* d_out, int out_size) {
    const float* x     = (const float*)d_in[0];
    const float* wih0f = (const float*)d_in[1];
    const float* whh0f = (const float*)d_in[2];
    const float* bih0f = (const float*)d_in[3];
    const float* bhh0f = (const float*)d_in[4];
    const float* wih0b = (const float*)d_in[5];
    const float* whh0b = (const float*)d_in[6];
    const float* bih0b = (const float*)d_in[7];
    const float* bhh0b = (const float*)d_in[8];
    const float* wih1f = (const float*)d_in[9];
    const float* whh1f = (const float*)d_in[10];
    const float* bih1f = (const float*)d_in[11];
    const float* bhh1f = (const float*)d_in[12];
    const float* wih1b = (const float*)d_in[13];
    const float* whh1b = (const float*)d_in[14];
    const float* bih1b = (const float*)d_in[15];
    const float* bhh1b = (const float*)d_in[16];
    const float* wout  = (const float*)d_in[17];
    const float* bout  = (const float*)d_in[18];
    float* out = (float*)d_out;

    k_gx0    <<<NTOK / 8, 768>>>(x, wih0f, bih0f, wih0b, bih0b);
    k_rec    <<<128, 384>>>(whh0f, bhh0f, whh0b, bhh0b);
    k_gemm_tc<<<dim3(2048, 3), 256>>>(wih1f, bih1f, wih1b, bih1b);
    k_rec    <<<128, 384>>>(whh1f, bhh1f, whh1b, bhh1b);
    k_head   <<<NTOK / 8, 256>>>(wout, bout, out);
}